// round 10
// baseline (speedup 1.0000x reference)
#include <cuda_runtime.h>
#include <cuda_fp16.h>
#include <cstdint>
#include <cstddef>

#define INNER 31999
#define VOCAB 32000
#define DEPTH 18
#define NROWS 64          // B*T
#define KDIM  512
#define MT    224         // nodes per block tile (143 blocks -> 1 per SM)
#define NBLK  143         // ceil(31999/224)
#define NPAD  (NBLK * MT) // 32032 padded node count
#define KC    64          // fp16 K elems per A chunk (=128B per row)
#define NCHUNK (KDIM / KC)       // 8
#define B_BYTES 65536            // 64 rows * 1024B (full K, fp16)
#define A_ST    28672            // 224 rows * 128B per stage
#define SMEM_TOTAL (B_BYTES + 2 * A_ST)   // 122880
#define NTHR  448                // 14 warps

// Log-prob table: [2*node + side][row], fp16. Padded to NPAD nodes.
__device__ __half g_L[(size_t)2 * NPAD * NROWS];

// ---------------- helpers ----------------
__device__ __forceinline__ uint32_t smem_u32(const void* p) {
    return (uint32_t)__cvta_generic_to_shared(p);
}
__device__ __forceinline__ void ldsm4(uint32_t& r0, uint32_t& r1, uint32_t& r2, uint32_t& r3,
                                      uint32_t addr) {
    asm volatile("ldmatrix.sync.aligned.m8n8.x4.shared.b16 {%0,%1,%2,%3}, [%4];"
                 : "=r"(r0), "=r"(r1), "=r"(r2), "=r"(r3) : "r"(addr));
}
__device__ __forceinline__ void mma_f16(float* c, const uint32_t* a, const uint32_t* b) {
    asm volatile(
        "mma.sync.aligned.m16n8k16.row.col.f32.f16.f16.f32 "
        "{%0,%1,%2,%3}, {%4,%5,%6,%7}, {%8,%9}, {%0,%1,%2,%3};"
        : "+f"(c[0]), "+f"(c[1]), "+f"(c[2]), "+f"(c[3])
        : "r"(a[0]), "r"(a[1]), "r"(a[2]), "r"(a[3]), "r"(b[0]), "r"(b[1]));
}
__device__ __forceinline__ void sts64(uint32_t off, __half2 p0, __half2 p1) {
    asm volatile("st.shared.v2.b32 [%0], {%1, %2};"
                 :: "r"(off), "r"(*(uint32_t*)&p0), "r"(*(uint32_t*)&p1));
}

// ---------------------------------------------------------------------------
// Kernel 1: C[224 nodes, 64 rows] per block = W_tile @ att^T. 143 blocks,
// exactly one per SM (122.9KB smem) -> balanced critical path at the
// mma.sync MAC ceiling. 448 threads = 14 M-warps, warp tile 16M x 64N.
// att fp32->fp16 once per block into K-resident smem B tile; A streams
// through a 2-stage ring (reg-staged LDG -> cvt -> STS).
// ---------------------------------------------------------------------------
__global__ __launch_bounds__(NTHR, 1) void hs_gemm_kernel(
    const float* __restrict__ att, const float* __restrict__ W)
{
    extern __shared__ char smem[];
    const uint32_t sb = smem_u32(smem);          // B at sb, A stages at sb+B_BYTES

    const int tid   = threadIdx.x;
    const int lane  = tid & 31;
    const int wm    = tid >> 5;                  // M-warp 0..13 (rows wm*16..+15)
    const int nbase = blockIdx.x * MT;
    const int gid   = lane >> 2;
    const int tig   = lane & 3;

    // -------- B prologue: att [64x512] fp32 -> fp16 smem, swizzled --------
    for (int j = tid; j < 8192; j += NTHR) {     // 64 rows x 128 float4
        int row = j >> 7, f4 = j & 127;
        float4 v = *reinterpret_cast<const float4*>(att + (size_t)row * KDIM + f4 * 4);
        uint32_t unit = (uint32_t)((f4 >> 1) ^ (row & 7));
        uint32_t off  = sb + (uint32_t)(row * 1024) + unit * 16 + (uint32_t)(f4 & 1) * 8;
        sts64(off, __floats2half2_rn(v.x, v.y), __floats2half2_rn(v.z, v.w));
    }

    // -------- A register staging: 8 float4 per thread per chunk --------
    float4 ra[8];
    auto ldg_stage = [&](int t) {
#pragma unroll
        for (int i = 0; i < 8; i++) {            // 224 rows x 16 float4 = 3584
            int u = tid + i * NTHR;
            int row = u >> 4, f4 = u & 15;
            int wr = nbase + row;
            if (wr < INNER)
                ra[i] = *reinterpret_cast<const float4*>(W + (size_t)wr * KDIM + t * KC + f4 * 4);
            else
                ra[i] = make_float4(0.f, 0.f, 0.f, 0.f);
        }
    };
    auto sts_A = [&](int buf) {
        const uint32_t base = sb + B_BYTES + (uint32_t)buf * A_ST;
#pragma unroll
        for (int i = 0; i < 8; i++) {
            int u = tid + i * NTHR;
            int row = u >> 4, f4 = u & 15;
            uint32_t unit = (uint32_t)((f4 >> 1) ^ (row & 7));
            uint32_t off  = base + (uint32_t)(row * 128) + unit * 16 + (uint32_t)(f4 & 1) * 8;
            sts64(off, __floats2half2_rn(ra[i].x, ra[i].y), __floats2half2_rn(ra[i].z, ra[i].w));
        }
    };

    // -------- ldmatrix per-lane address precompute --------
    const int li = lane >> 3;
    const int lr = lane & 7;
    const uint32_t kh = (uint32_t)(li >> 1);     // k 16B-half select
    uint32_t aBase, aX;
    {
        int row = wm * 16 + lr + ((li & 1) << 3);
        aBase = sb + B_BYTES + (uint32_t)(row * 128);
        aX    = (uint32_t)(row & 7);
    }
    uint32_t bBase[4], bX[4];
#pragma unroll
    for (int q = 0; q < 4; q++) {
        int row = q * 16 + lr + ((li & 1) << 3);
        bBase[q] = sb + (uint32_t)(row * 1024);
        bX[q]    = (uint32_t)(row & 7);
    }

    float acc[8][4];
#pragma unroll
    for (int f = 0; f < 8; f++)
#pragma unroll
        for (int c = 0; c < 4; c++) acc[f][c] = 0.0f;

    // -------- prologue: A stage 0 in smem, stage 1 in regs --------
    ldg_stage(0);
    sts_A(0);
    ldg_stage(1);
    __syncthreads();                             // B tile + A stage 0 visible

    for (int t = 0; t < NCHUNK; t++) {
        if (t + 1 < NCHUNK) sts_A((t + 1) & 1);
        if (t + 2 < NCHUNK) ldg_stage(t + 2);

        const uint32_t Ab = (uint32_t)(t & 1) * A_ST;
#pragma unroll
        for (int ks = 0; ks < 4; ks++) {         // 4 x k16 per chunk
            uint32_t a[4];
            ldsm4(a[0], a[1], a[2], a[3],
                  aBase + Ab + ((((uint32_t)(ks * 2) + kh) ^ aX) << 4));
            uint32_t b[8][2];
            const uint32_t ksg2 = (uint32_t)(t * 8 + ks * 2);   // global k unit
#pragma unroll
            for (int q = 0; q < 4; q++) {
                uint32_t r0, r1, r2, r3;
                ldsm4(r0, r1, r2, r3, bBase[q] + (((ksg2 + kh) ^ bX[q]) << 4));
                b[q * 2][0] = r0;     b[q * 2][1] = r2;
                b[q * 2 + 1][0] = r1; b[q * 2 + 1][1] = r3;
            }
#pragma unroll
            for (int f = 0; f < 8; f++)
                mma_f16(acc[f], a, b[f]);
        }
        __syncthreads();
    }

    // -------- epilogue: softplus -> fp16, smem transpose (swizzled), flat copy --------
#pragma unroll
    for (int m8 = 0; m8 < 2; m8++) {
        const int nl = wm * 16 + m8 * 8 + gid;   // local node 0..223
        const uint32_t swz = (uint32_t)((nl & 7) << 4);
#pragma unroll
        for (int f = 0; f < 8; f++) {
            float lp[2], ln[2];
#pragma unroll
            for (int u = 0; u < 2; u++) {
                float h = acc[f][m8 * 2 + u];
                float l = __logf(1.0f + __expf(-fabsf(h)));
                lp[u] = fmaxf(fminf(h, 0.0f) - l, -20.7232658f);   // log sigma
                ln[u] = fmaxf(-fmaxf(h, 0.0f) - l, -20.7232658f);  // log(1-sigma)
            }
            const uint32_t col = (uint32_t)(f * 16 + tig * 4) ^ swz;
            *reinterpret_cast<__half2*>(smem + (2 * nl)     * 128 + col) = __floats2half2_rn(lp[0], lp[1]);
            *reinterpret_cast<__half2*>(smem + (2 * nl + 1) * 128 + col) = __floats2half2_rn(ln[0], ln[1]);
        }
    }
    __syncthreads();

    char* gdst = reinterpret_cast<char*>(&g_L[(size_t)(2 * nbase) * NROWS]);
#pragma unroll
    for (int i = 0; i < 8; i++) {
        int u = tid + i * NTHR;                  // 16B unit, 0..3583
        int s = u >> 3, j = u & 7;
        uint32_t soff = (uint32_t)(s * 128 + ((j ^ ((s >> 1) & 7)) << 4));
        uint4 v = *reinterpret_cast<const uint4*>(smem + soff);
        *reinterpret_cast<uint4*>(gdst + (size_t)u * 16) = v;
    }
}

// ---------------------------------------------------------------------------
// Kernel 2: 32 words per block (8 warps x 4 words), 256 threads, grid 1000.
// LDG.128 table reads: one warp-load covers a full 128B row for 4 words
// (lane group g=lane>>3 -> word, sub=lane&7 -> rows 8*sub..+7).
// 18 batched LDG.128 per warp; pairwise HADD2 + fp32 flush per depth-pair.
// ---------------------------------------------------------------------------
#define GWPB 32
__global__ __launch_bounds__(256) void hs_gather_kernel(
    const int* __restrict__ pidx, const float* __restrict__ psign,
    float* __restrict__ out)
{
    __shared__ uint16_t sci[GWPB * DEPTH];      // 576 packed child indices
    __shared__ float tr[NROWS * (GWPB + 1)];    // [row][word], pad 33

    const int tid   = threadIdx.x;
    const int lane  = tid & 31;
    const int warp  = tid >> 5;
    const int g     = lane >> 3;                 // word-in-warp 0..3
    const int sub   = lane & 7;                  // 16B sub-chunk -> rows 8*sub..+7
    const int wbase = blockIdx.x * GWPB;

    for (int j = tid; j < GWPB * DEPTH; j += 256) {
        int gj = wbase * DEPTH + j;
        sci[j] = (uint16_t)(2 * pidx[gj] + (psign[gj] < 0.0f ? 1 : 0));
    }
    __syncthreads();

    const int wloc = warp * 4 + g;               // word within block 0..31

    // Batch all 18 row-chunk loads (independent -> deep MLP)
    uint4 v[DEPTH];
#pragma unroll
    for (int d = 0; d < DEPTH; d++) {
        int ci = sci[wloc * DEPTH + d];
        v[d] = __ldg(reinterpret_cast<const uint4*>(&g_L[(size_t)ci * NROWS]) + sub);
    }

    // Reduce: pairwise fp16 add, then fp32 accumulate (9 flushes)
    float acc[8] = {0.f, 0.f, 0.f, 0.f, 0.f, 0.f, 0.f, 0.f};
#pragma unroll
    for (int p = 0; p < DEPTH / 2; p++) {
        const uint4 a = v[2 * p], b = v[2 * p + 1];
        __half2 s0 = __hadd2(*(const __half2*)&a.x, *(const __half2*)&b.x);
        __half2 s1 = __hadd2(*(const __half2*)&a.y, *(const __half2*)&b.y);
        __half2 s2 = __hadd2(*(const __half2*)&a.z, *(const __half2*)&b.z);
        __half2 s3 = __hadd2(*(const __half2*)&a.w, *(const __half2*)&b.w);
        float2 f0 = __half22float2(s0); acc[0] += f0.x; acc[1] += f0.y;
        float2 f1 = __half22float2(s1); acc[2] += f1.x; acc[3] += f1.y;
        float2 f2 = __half22float2(s2); acc[4] += f2.x; acc[5] += f2.y;
        float2 f3 = __half22float2(s3); acc[6] += f3.x; acc[7] += f3.y;
    }

    // rows 8*sub + r, word wloc
#pragma unroll
    for (int r = 0; r < 8; r++)
        tr[(8 * sub + r) * (GWPB + 1) + wloc] = acc[r];
    __syncthreads();

    // 64 rows x 32 words = 2048 floats = 512 float4; 2 per thread
#pragma unroll
    for (int i = 0; i < 2; i++) {
        int u   = tid + i * 256;
        int row = u >> 3;
        int q   = (u & 7) * 4;
        float4 o = make_float4(tr[row * (GWPB + 1) + q],     tr[row * (GWPB + 1) + q + 1],
                               tr[row * (GWPB + 1) + q + 2], tr[row * (GWPB + 1) + q + 3]);
        *reinterpret_cast<float4*>(out + (size_t)row * VOCAB + wbase + q) = o;
    }
}

extern "C" void kernel_launch(void* const* d_in, const int* in_sizes, int n_in,
                              void* d_out, int out_size)
{
    (void)in_sizes; (void)n_in; (void)out_size;
    const float* att   = (const float*)d_in[0];
    const float* W     = (const float*)d_in[1];
    const int*   pidx  = (const int*)d_in[2];
    const float* psign = (const float*)d_in[3];
    float* out = (float*)d_out;

    cudaFuncSetAttribute(hs_gemm_kernel, cudaFuncAttributeMaxDynamicSharedMemorySize, SMEM_TOTAL);
    hs_gemm_kernel<<<NBLK, NTHR, SMEM_TOTAL>>>(att, W);
    hs_gather_kernel<<<VOCAB / GWPB, 256>>>(pidx, psign, out);
}